// round 2
// baseline (speedup 1.0000x reference)
#include <cuda_runtime.h>
#include <cuda_bf16.h>
#include <cstdint>

// ---------------------------------------------------------------------------
// Problem constants (match reference_code)
// ---------------------------------------------------------------------------
#define N_SRC0 700000
#define N_SRC1 51200
#define N_SRC2 5120
#define N_DST0 51200
#define N_DST1 5120
#define N_DST2 1024
#define N_EDGE0 768000
#define N_EDGE1 51200
#define N_EDGE2 5120
#define IN_FEATS 128
#define N_HIDDEN 256
#define N_CLASSES 47

// ---------------------------------------------------------------------------
// Scratch (no allocations allowed -> __device__ globals).
// __align__(16): device float arrays only guarantee 4B natural alignment,
// but we access them with float4 / red.v4.f32.
// ---------------------------------------------------------------------------
__device__ __align__(16) float g_msg0[(size_t)N_DST0 * IN_FEATS];   // 26.2 MB
__device__ __align__(16) float g_deg0[N_DST0];
__device__ __align__(16) float g_h1[(size_t)N_DST0 * N_HIDDEN];     // 52.4 MB
__device__ __align__(16) float g_msg1[(size_t)N_DST1 * N_HIDDEN];   // 5.2 MB
__device__ __align__(16) float g_deg1[N_DST1];
__device__ __align__(16) float g_h2[(size_t)N_DST1 * N_HIDDEN];     // 5.2 MB
__device__ __align__(16) float g_msg2[(size_t)N_DST2 * N_HIDDEN];   // 1.0 MB
__device__ __align__(16) float g_deg2[N_DST2];

// ---------------------------------------------------------------------------
// Helpers
// ---------------------------------------------------------------------------
__device__ __forceinline__ void red_add_v4(float* addr, float4 v) {
    // sm_90+: vectorized f32 reduction, 1 L2 transaction per 16B instead of 4
    asm volatile("red.global.add.v4.f32 [%0], {%1, %2, %3, %4};"
                 :: "l"(addr), "f"(v.x), "f"(v.y), "f"(v.z), "f"(v.w)
                 : "memory");
}

// ---------------------------------------------------------------------------
// Zero-fill
// ---------------------------------------------------------------------------
__global__ void zero_kernel(float* __restrict__ p, int n4 /* count of float4 */) {
    int i = blockIdx.x * blockDim.x + threadIdx.x;
    if (i < n4) reinterpret_cast<float4*>(p)[i] = make_float4(0.f, 0.f, 0.f, 0.f);
}

__global__ void zero_kernel_s(float* __restrict__ p, int n) {
    int i = blockIdx.x * blockDim.x + threadIdx.x;
    if (i < n) p[i] = 0.f;
}

// ---------------------------------------------------------------------------
// Edge aggregation: msg[dst] += h[src], deg[dst] += 1
// F/4 lanes cooperate on one edge (32 lanes for F=128, 64 for F=256).
// ---------------------------------------------------------------------------
template <int F>
__global__ __launch_bounds__(256)
void aggregate_kernel(const float* __restrict__ h,
                      const int* __restrict__ src,
                      const int* __restrict__ dst,
                      float* __restrict__ msg,
                      float* __restrict__ deg,
                      int n_edge) {
    constexpr int LPE = F / 4;                 // lanes per edge
    int gtid = blockIdx.x * blockDim.x + threadIdx.x;
    int e    = gtid / LPE;
    int lane = gtid % LPE;
    if (e >= n_edge) return;

    int s = src[e];
    int d = dst[e];

    float4 v = reinterpret_cast<const float4*>(h + (size_t)s * F)[lane];
    red_add_v4(msg + (size_t)d * F + (size_t)lane * 4, v);

    if (lane == 0) atomicAdd(&deg[d], 1.0f);
}

// ---------------------------------------------------------------------------
// h_neigh = msg / max(deg, 1)  (in place)
// ---------------------------------------------------------------------------
template <int F>
__global__ void divide_kernel(float* __restrict__ msg,
                              const float* __restrict__ deg,
                              int n_dst) {
    int i = blockIdx.x * blockDim.x + threadIdx.x;   // float4 index
    int total = n_dst * (F / 4);
    if (i >= total) return;
    int row = i / (F / 4);
    float dnv = 1.0f / fmaxf(deg[row], 1.0f);
    float4 v = reinterpret_cast<float4*>(msg)[i];
    v.x *= dnv; v.y *= dnv; v.z *= dnv; v.w *= dnv;
    reinterpret_cast<float4*>(msg)[i] = v;
}

// ---------------------------------------------------------------------------
// Fused dual GEMM: C = A1 @ B1 + A2 @ B2 + bias  (+ optional ReLU)
// A1, A2 : [M, K] row-major, 16B-aligned bases, K % 16 == 0
// B1, B2 : [K, N] row-major (vector path only if N % 4 == 0)
// Tiling: BM=128, BN=64, BK=16, 256 threads, 8x4 micro-tile per thread.
// ---------------------------------------------------------------------------
template <bool RELU>
__global__ __launch_bounds__(256)
void gemm2_kernel(const float* __restrict__ A1, const float* __restrict__ A2,
                  const float* __restrict__ B1, const float* __restrict__ B2,
                  const float* __restrict__ bias, float* __restrict__ C,
                  int M, int N, int K) {
    constexpr int BM = 128, BN = 64, BK = 16, TM = 8, TN = 4;

    __shared__ float As[BK][BM];
    __shared__ float Bs[BK][BN];

    const int tid = threadIdx.x;
    const int tx  = tid & 15;    // 0..15 -> column group
    const int ty  = tid >> 4;    // 0..15 -> row group
    const int rowBase = blockIdx.y * BM;
    const int colBase = blockIdx.x * BN;
    const bool nvec = (N & 3) == 0;   // B rows 16B-aligned only then

    float acc[TM][TN];
#pragma unroll
    for (int i = 0; i < TM; ++i)
#pragma unroll
        for (int j = 0; j < TN; ++j) acc[i][j] = 0.f;

#pragma unroll
    for (int phase = 0; phase < 2; ++phase) {
        const float* __restrict__ A = phase ? A2 : A1;
        const float* __restrict__ B = phase ? B2 : B1;

        for (int k0 = 0; k0 < K; k0 += BK) {
            // --- load A tile (128x16) as float4, transposed into As[k][m] ---
#pragma unroll
            for (int i = 0; i < 2; ++i) {
                int idx  = tid * 2 + i;          // 0..511 float4 slots
                int aRow = idx >> 2;             // 0..127
                int aC4  = idx & 3;              // 0..3
                float4 v = *reinterpret_cast<const float4*>(
                    A + (size_t)(rowBase + aRow) * K + k0 + aC4 * 4);
                As[aC4 * 4 + 0][aRow] = v.x;
                As[aC4 * 4 + 1][aRow] = v.y;
                As[aC4 * 4 + 2][aRow] = v.z;
                As[aC4 * 4 + 3][aRow] = v.w;
            }
            // --- load B tile (16x64), one float4 per thread, N-guarded ---
            {
                int bRow = tid >> 4;             // 0..15
                int bC4  = tid & 15;             // 0..15
                int col  = colBase + bC4 * 4;
                const float* bp = B + (size_t)(k0 + bRow) * N;
                float4 v;
                if (nvec && col + 3 < N) {
                    v = *reinterpret_cast<const float4*>(bp + col);
                } else {
                    // scalar fallback: handles N % 4 != 0 (misaligned rows)
                    v.x = (col + 0 < N) ? bp[col + 0] : 0.f;
                    v.y = (col + 1 < N) ? bp[col + 1] : 0.f;
                    v.z = (col + 2 < N) ? bp[col + 2] : 0.f;
                    v.w = (col + 3 < N) ? bp[col + 3] : 0.f;
                }
                *reinterpret_cast<float4*>(&Bs[bRow][bC4 * 4]) = v;
            }
            __syncthreads();

#pragma unroll
            for (int kk = 0; kk < BK; ++kk) {
                float a[TM];
#pragma unroll
                for (int i = 0; i < TM; ++i) a[i] = As[kk][ty * TM + i];
                float4 bv = *reinterpret_cast<float4*>(&Bs[kk][tx * TN]);
                float b[TN] = {bv.x, bv.y, bv.z, bv.w};
#pragma unroll
                for (int i = 0; i < TM; ++i)
#pragma unroll
                    for (int j = 0; j < TN; ++j) acc[i][j] += a[i] * b[j];
            }
            __syncthreads();
        }
    }

    // --- epilogue: bias (+ReLU), N-guarded scalar stores ---
#pragma unroll
    for (int i = 0; i < TM; ++i) {
        int r = rowBase + ty * TM + i;
#pragma unroll
        for (int j = 0; j < TN; ++j) {
            int c = colBase + tx * TN + j;
            if (c < N) {
                float v = acc[i][j] + bias[c];
                if (RELU) v = fmaxf(v, 0.f);
                C[(size_t)r * N + c] = v;
            }
        }
    }
}

// ---------------------------------------------------------------------------
// Launch
// ---------------------------------------------------------------------------
static inline int cdiv(int a, int b) { return (a + b - 1) / b; }

extern "C" void kernel_launch(void* const* d_in, const int* in_sizes, int n_in,
                              void* d_out, int out_size) {
    // Input order: x, src0, dst0, src1, dst1, src2, dst2,
    //              Ws0, Wn0, b0, Ws1, Wn1, b1, Ws2, Wn2, b2
    const float* x    = (const float*)d_in[0];
    const int*   src0 = (const int*)d_in[1];
    const int*   dst0 = (const int*)d_in[2];
    const int*   src1 = (const int*)d_in[3];
    const int*   dst1 = (const int*)d_in[4];
    const int*   src2 = (const int*)d_in[5];
    const int*   dst2 = (const int*)d_in[6];
    const float* Ws0  = (const float*)d_in[7];
    const float* Wn0  = (const float*)d_in[8];
    const float* b0   = (const float*)d_in[9];
    const float* Ws1  = (const float*)d_in[10];
    const float* Wn1  = (const float*)d_in[11];
    const float* b1   = (const float*)d_in[12];
    const float* Ws2  = (const float*)d_in[13];
    const float* Wn2  = (const float*)d_in[14];
    const float* b2   = (const float*)d_in[15];
    float* out = (float*)d_out;

    float *msg0, *deg0, *h1, *msg1, *deg1, *h2, *msg2, *deg2;
    cudaGetSymbolAddress((void**)&msg0, g_msg0);
    cudaGetSymbolAddress((void**)&deg0, g_deg0);
    cudaGetSymbolAddress((void**)&h1,   g_h1);
    cudaGetSymbolAddress((void**)&msg1, g_msg1);
    cudaGetSymbolAddress((void**)&deg1, g_deg1);
    cudaGetSymbolAddress((void**)&h2,   g_h2);
    cudaGetSymbolAddress((void**)&msg2, g_msg2);
    cudaGetSymbolAddress((void**)&deg2, g_deg2);

    const int TPB = 256;

    // ======================= Layer 0 =======================
    {
        int n4 = N_DST0 * IN_FEATS / 4;
        zero_kernel<<<cdiv(n4, TPB), TPB>>>(msg0, n4);
        zero_kernel_s<<<cdiv(N_DST0, TPB), TPB>>>(deg0, N_DST0);

        long long threads = (long long)N_EDGE0 * (IN_FEATS / 4);
        aggregate_kernel<IN_FEATS><<<(int)((threads + TPB - 1) / TPB), TPB>>>(
            x, src0, dst0, msg0, deg0, N_EDGE0);

        divide_kernel<IN_FEATS><<<cdiv(n4, TPB), TPB>>>(msg0, deg0, N_DST0);

        dim3 grid(cdiv(N_HIDDEN, 64), N_DST0 / 128);
        gemm2_kernel<true><<<grid, 256>>>(x, msg0, Ws0, Wn0, b0, h1,
                                          N_DST0, N_HIDDEN, IN_FEATS);
    }

    // ======================= Layer 1 =======================
    {
        int n4 = N_DST1 * N_HIDDEN / 4;
        zero_kernel<<<cdiv(n4, TPB), TPB>>>(msg1, n4);
        zero_kernel_s<<<cdiv(N_DST1, TPB), TPB>>>(deg1, N_DST1);

        long long threads = (long long)N_EDGE1 * (N_HIDDEN / 4);
        aggregate_kernel<N_HIDDEN><<<(int)((threads + TPB - 1) / TPB), TPB>>>(
            h1, src1, dst1, msg1, deg1, N_EDGE1);

        divide_kernel<N_HIDDEN><<<cdiv(n4, TPB), TPB>>>(msg1, deg1, N_DST1);

        dim3 grid(cdiv(N_HIDDEN, 64), N_DST1 / 128);
        gemm2_kernel<true><<<grid, 256>>>(h1, msg1, Ws1, Wn1, b1, h2,
                                          N_DST1, N_HIDDEN, N_HIDDEN);
    }

    // ======================= Layer 2 =======================
    {
        int n4 = N_DST2 * N_HIDDEN / 4;
        zero_kernel<<<cdiv(n4, TPB), TPB>>>(msg2, n4);
        zero_kernel_s<<<cdiv(N_DST2, TPB), TPB>>>(deg2, N_DST2);

        long long threads = (long long)N_EDGE2 * (N_HIDDEN / 4);
        aggregate_kernel<N_HIDDEN><<<(int)((threads + TPB - 1) / TPB), TPB>>>(
            h2, src2, dst2, msg2, deg2, N_EDGE2);

        divide_kernel<N_HIDDEN><<<cdiv(n4, TPB), TPB>>>(msg2, deg2, N_DST2);

        dim3 grid(cdiv(N_CLASSES, 64), N_DST2 / 128);
        gemm2_kernel<false><<<grid, 256>>>(h2, msg2, Ws2, Wn2, b2, out,
                                           N_DST2, N_CLASSES, N_HIDDEN);
    }

    (void)in_sizes; (void)n_in; (void)out_size;
}

// round 3
// speedup vs baseline: 1.4860x; 1.4860x over previous
#include <cuda_runtime.h>
#include <cuda_bf16.h>
#include <cstdint>

// ---------------------------------------------------------------------------
// Problem constants
// ---------------------------------------------------------------------------
#define N_SRC0 700000
#define N_DST0 51200
#define N_DST1 5120
#define N_DST2 1024
#define N_EDGE0 768000
#define N_EDGE1 51200
#define N_EDGE2 5120
#define IN_FEATS 128
#define N_HIDDEN 256
#define N_CLASSES 47

// ---------------------------------------------------------------------------
// Scratch (__device__ globals; 16B aligned for float4 / red.v4)
// ---------------------------------------------------------------------------
__device__ __align__(16) float g_msg0[(size_t)N_DST0 * IN_FEATS];
__device__ __align__(16) float g_deg0[N_DST0];
__device__ __align__(16) float g_h1[(size_t)N_DST0 * N_HIDDEN];
__device__ __align__(16) float g_msg1[(size_t)N_DST1 * N_HIDDEN];
__device__ __align__(16) float g_deg1[N_DST1];
__device__ __align__(16) float g_h2[(size_t)N_DST1 * N_HIDDEN];
__device__ __align__(16) float g_msg2[(size_t)N_DST2 * N_HIDDEN];
__device__ __align__(16) float g_deg2[N_DST2];

// ---------------------------------------------------------------------------
// Helpers
// ---------------------------------------------------------------------------
__device__ __forceinline__ void red_add_v4(float* addr, float4 v) {
    asm volatile("red.global.add.v4.f32 [%0], {%1, %2, %3, %4};"
                 :: "l"(addr), "f"(v.x), "f"(v.y), "f"(v.z), "f"(v.w)
                 : "memory");
}

__device__ __forceinline__ uint32_t f2tf32(float f) {
    uint32_t u;
    asm("cvt.rna.tf32.f32 %0, %1;" : "=r"(u) : "f"(f));
    return u;
}

__device__ __forceinline__ void mma_tf32(float& c0, float& c1, float& c2, float& c3,
                                         uint32_t a0, uint32_t a1, uint32_t a2, uint32_t a3,
                                         uint32_t b0, uint32_t b1) {
    asm volatile("mma.sync.aligned.m16n8k8.row.col.f32.tf32.tf32.f32 "
                 "{%0,%1,%2,%3}, {%4,%5,%6,%7}, {%8,%9}, {%0,%1,%2,%3};"
                 : "+f"(c0), "+f"(c1), "+f"(c2), "+f"(c3)
                 : "r"(a0), "r"(a1), "r"(a2), "r"(a3), "r"(b0), "r"(b1));
}

// ---------------------------------------------------------------------------
// Small utility kernels
// ---------------------------------------------------------------------------
__global__ void zero_kernel(float* __restrict__ p, int n4) {
    int i = blockIdx.x * blockDim.x + threadIdx.x;
    if (i < n4) reinterpret_cast<float4*>(p)[i] = make_float4(0.f, 0.f, 0.f, 0.f);
}

__global__ void zero_kernel_s(float* __restrict__ p, int n) {
    int i = blockIdx.x * blockDim.x + threadIdx.x;
    if (i < n) p[i] = 0.f;
}

// deg -> 1 / max(deg, 1)
__global__ void inv_kernel(float* __restrict__ deg, int n) {
    int i = blockIdx.x * blockDim.x + threadIdx.x;
    if (i < n) deg[i] = 1.0f / fmaxf(deg[i], 1.0f);
}

// ---------------------------------------------------------------------------
// Edge aggregation: msg[dst] += h[src], deg[dst] += 1
// ---------------------------------------------------------------------------
template <int F>
__global__ __launch_bounds__(256)
void aggregate_kernel(const float* __restrict__ h,
                      const int* __restrict__ src,
                      const int* __restrict__ dst,
                      float* __restrict__ msg,
                      float* __restrict__ deg,
                      int n_edge) {
    constexpr int LPE = F / 4;
    int gtid = blockIdx.x * blockDim.x + threadIdx.x;
    int e    = gtid / LPE;
    int lane = gtid % LPE;
    if (e >= n_edge) return;

    int s = src[e];
    int d = dst[e];

    float4 v = reinterpret_cast<const float4*>(h + (size_t)s * F)[lane];
    red_add_v4(msg + (size_t)d * F + (size_t)lane * 4, v);

    if (lane == 0) atomicAdd(&deg[d], 1.0f);
}

// ---------------------------------------------------------------------------
// tf32 tensor-core dual GEMM:
//   C = A1 @ B1 + diag(rdeg) * A2 @ B2 + bias   (+ optional ReLU)
// Requires: M % 128 == 0, N % 128 == 0, K % 32 == 0, 16B-aligned pointers.
// BM=128, BN=128, BK=32; 8 warps, each computing a 64x32 warp tile
// (4 m-tiles x 4 n-tiles of m16n8k8).
// ---------------------------------------------------------------------------
template <bool RELU>
__global__ __launch_bounds__(256)
void gemm2_tc_kernel(const float* __restrict__ A1, const float* __restrict__ A2,
                     const float* __restrict__ rdeg,
                     const float* __restrict__ B1, const float* __restrict__ B2,
                     const float* __restrict__ bias, float* __restrict__ C,
                     int M, int N, int K) {
    constexpr int BM = 128, BN = 128, BK = 32;

    __shared__ uint32_t As[BM][BK + 4];   // row-major (m, k), tf32 bits
    __shared__ uint32_t Bs[BK][BN + 8];   // row-major (k, n), tf32 bits

    const int tid   = threadIdx.x;
    const int warp  = tid >> 5;
    const int lane  = tid & 31;
    const int g     = lane >> 2;   // group id 0..7
    const int t     = lane & 3;    // thread-in-group 0..3
    const int warpM = (warp & 1) * 64;   // 2 warps along M
    const int warpN = (warp >> 1) * 32;  // 4 warps along N
    const int rowBase = blockIdx.y * BM;
    const int colBase = blockIdx.x * BN;

    float acc[4][4][4];   // [m-tile][n-tile][c0..c3]
#pragma unroll
    for (int i = 0; i < 4; ++i)
#pragma unroll
        for (int j = 0; j < 4; ++j)
#pragma unroll
            for (int r = 0; r < 4; ++r) acc[i][j][r] = 0.f;

#pragma unroll
    for (int phase = 0; phase < 2; ++phase) {
        const float* __restrict__ A = phase ? A2 : A1;
        const float* __restrict__ B = phase ? B2 : B1;

        for (int k0 = 0; k0 < K; k0 += BK) {
            // --- A tile: 128x32 floats = 1024 float4, 4 per thread ---
#pragma unroll
            for (int i = 0; i < 4; ++i) {
                int idx = i * 256 + tid;
                int row = idx >> 3;       // 0..127
                int c4  = idx & 7;        // 0..7
                float4 v = *reinterpret_cast<const float4*>(
                    A + (size_t)(rowBase + row) * K + k0 + c4 * 4);
                if (phase == 1) {
                    float s = rdeg[rowBase + row];
                    v.x *= s; v.y *= s; v.z *= s; v.w *= s;
                }
                uint4 u = make_uint4(f2tf32(v.x), f2tf32(v.y), f2tf32(v.z), f2tf32(v.w));
                *reinterpret_cast<uint4*>(&As[row][c4 * 4]) = u;
            }
            // --- B tile: 32x128 floats = 1024 float4, 4 per thread ---
#pragma unroll
            for (int i = 0; i < 4; ++i) {
                int idx = i * 256 + tid;
                int row = idx >> 5;       // 0..31
                int c4  = idx & 31;       // 0..31
                float4 v = *reinterpret_cast<const float4*>(
                    B + (size_t)(k0 + row) * N + colBase + c4 * 4);
                uint4 u = make_uint4(f2tf32(v.x), f2tf32(v.y), f2tf32(v.z), f2tf32(v.w));
                *reinterpret_cast<uint4*>(&Bs[row][c4 * 4]) = u;
            }
            __syncthreads();

#pragma unroll
            for (int ks = 0; ks < BK / 8; ++ks) {
                const int kb = ks * 8;
                // A fragments for 4 m-tiles (conflict-free: bank == lane)
                uint32_t af[4][4];
#pragma unroll
                for (int mt = 0; mt < 4; ++mt) {
                    int m = warpM + mt * 16;
                    af[mt][0] = As[m + g][kb + t];
                    af[mt][1] = As[m + 8 + g][kb + t];
                    af[mt][2] = As[m + g][kb + 4 + t];
                    af[mt][3] = As[m + 8 + g][kb + 4 + t];
                }
                // B fragments for 4 n-tiles (conflict-free)
                uint32_t bf[4][2];
#pragma unroll
                for (int nt = 0; nt < 4; ++nt) {
                    int n = warpN + nt * 8;
                    bf[nt][0] = Bs[kb + t][n + g];
                    bf[nt][1] = Bs[kb + 4 + t][n + g];
                }
#pragma unroll
                for (int mt = 0; mt < 4; ++mt)
#pragma unroll
                    for (int nt = 0; nt < 4; ++nt)
                        mma_tf32(acc[mt][nt][0], acc[mt][nt][1],
                                 acc[mt][nt][2], acc[mt][nt][3],
                                 af[mt][0], af[mt][1], af[mt][2], af[mt][3],
                                 bf[nt][0], bf[nt][1]);
            }
            __syncthreads();
        }
    }

    // --- epilogue: bias (+ReLU), float2 stores ---
#pragma unroll
    for (int mt = 0; mt < 4; ++mt) {
#pragma unroll
        for (int nt = 0; nt < 4; ++nt) {
            int c  = colBase + warpN + nt * 8 + 2 * t;
            float bx = bias[c], by = bias[c + 1];
            int r0 = rowBase + warpM + mt * 16 + g;
            float v0 = acc[mt][nt][0] + bx;
            float v1 = acc[mt][nt][1] + by;
            float v2 = acc[mt][nt][2] + bx;
            float v3 = acc[mt][nt][3] + by;
            if (RELU) {
                v0 = fmaxf(v0, 0.f); v1 = fmaxf(v1, 0.f);
                v2 = fmaxf(v2, 0.f); v3 = fmaxf(v3, 0.f);
            }
            *reinterpret_cast<float2*>(C + (size_t)r0 * N + c)       = make_float2(v0, v1);
            *reinterpret_cast<float2*>(C + (size_t)(r0 + 8) * N + c) = make_float2(v2, v3);
        }
    }
}

// ---------------------------------------------------------------------------
// SIMT dual GEMM (layer 2: N=47). A2 rows scaled by rdeg at load.
// ---------------------------------------------------------------------------
template <bool RELU>
__global__ __launch_bounds__(256)
void gemm2_kernel(const float* __restrict__ A1, const float* __restrict__ A2,
                  const float* __restrict__ rdeg,
                  const float* __restrict__ B1, const float* __restrict__ B2,
                  const float* __restrict__ bias, float* __restrict__ C,
                  int M, int N, int K) {
    constexpr int BM = 128, BN = 64, BK = 16, TM = 8, TN = 4;

    __shared__ float As[BK][BM];
    __shared__ float Bs[BK][BN];

    const int tid = threadIdx.x;
    const int tx  = tid & 15;
    const int ty  = tid >> 4;
    const int rowBase = blockIdx.y * BM;
    const int colBase = blockIdx.x * BN;
    const bool nvec = (N & 3) == 0;

    float acc[TM][TN];
#pragma unroll
    for (int i = 0; i < TM; ++i)
#pragma unroll
        for (int j = 0; j < TN; ++j) acc[i][j] = 0.f;

#pragma unroll
    for (int phase = 0; phase < 2; ++phase) {
        const float* __restrict__ A = phase ? A2 : A1;
        const float* __restrict__ B = phase ? B2 : B1;

        for (int k0 = 0; k0 < K; k0 += BK) {
#pragma unroll
            for (int i = 0; i < 2; ++i) {
                int idx  = tid * 2 + i;
                int aRow = idx >> 2;
                int aC4  = idx & 3;
                float4 v = *reinterpret_cast<const float4*>(
                    A + (size_t)(rowBase + aRow) * K + k0 + aC4 * 4);
                if (phase == 1) {
                    float s = rdeg[rowBase + aRow];
                    v.x *= s; v.y *= s; v.z *= s; v.w *= s;
                }
                As[aC4 * 4 + 0][aRow] = v.x;
                As[aC4 * 4 + 1][aRow] = v.y;
                As[aC4 * 4 + 2][aRow] = v.z;
                As[aC4 * 4 + 3][aRow] = v.w;
            }
            {
                int bRow = tid >> 4;
                int bC4  = tid & 15;
                int col  = colBase + bC4 * 4;
                const float* bp = B + (size_t)(k0 + bRow) * N;
                float4 v;
                if (nvec && col + 3 < N) {
                    v = *reinterpret_cast<const float4*>(bp + col);
                } else {
                    v.x = (col + 0 < N) ? bp[col + 0] : 0.f;
                    v.y = (col + 1 < N) ? bp[col + 1] : 0.f;
                    v.z = (col + 2 < N) ? bp[col + 2] : 0.f;
                    v.w = (col + 3 < N) ? bp[col + 3] : 0.f;
                }
                *reinterpret_cast<float4*>(&Bs[bRow][bC4 * 4]) = v;
            }
            __syncthreads();

#pragma unroll
            for (int kk = 0; kk < BK; ++kk) {
                float a[TM];
#pragma unroll
                for (int i = 0; i < TM; ++i) a[i] = As[kk][ty * TM + i];
                float4 bv = *reinterpret_cast<float4*>(&Bs[kk][tx * TN]);
                float b[TN] = {bv.x, bv.y, bv.z, bv.w};
#pragma unroll
                for (int i = 0; i < TM; ++i)
#pragma unroll
                    for (int j = 0; j < TN; ++j) acc[i][j] += a[i] * b[j];
            }
            __syncthreads();
        }
    }

#pragma unroll
    for (int i = 0; i < TM; ++i) {
        int r = rowBase + ty * TM + i;
#pragma unroll
        for (int j = 0; j < TN; ++j) {
            int c = colBase + tx * TN + j;
            if (c < N) {
                float v = acc[i][j] + bias[c];
                if (RELU) v = fmaxf(v, 0.f);
                C[(size_t)r * N + c] = v;
            }
        }
    }
}

// ---------------------------------------------------------------------------
// Launch
// ---------------------------------------------------------------------------
static inline int cdiv(int a, int b) { return (a + b - 1) / b; }

extern "C" void kernel_launch(void* const* d_in, const int* in_sizes, int n_in,
                              void* d_out, int out_size) {
    const float* x    = (const float*)d_in[0];
    const int*   src0 = (const int*)d_in[1];
    const int*   dst0 = (const int*)d_in[2];
    const int*   src1 = (const int*)d_in[3];
    const int*   dst1 = (const int*)d_in[4];
    const int*   src2 = (const int*)d_in[5];
    const int*   dst2 = (const int*)d_in[6];
    const float* Ws0  = (const float*)d_in[7];
    const float* Wn0  = (const float*)d_in[8];
    const float* b0   = (const float*)d_in[9];
    const float* Ws1  = (const float*)d_in[10];
    const float* Wn1  = (const float*)d_in[11];
    const float* b1   = (const float*)d_in[12];
    const float* Ws2  = (const float*)d_in[13];
    const float* Wn2  = (const float*)d_in[14];
    const float* b2   = (const float*)d_in[15];
    float* out = (float*)d_out;

    float *msg0, *deg0, *h1, *msg1, *deg1, *h2, *msg2, *deg2;
    cudaGetSymbolAddress((void**)&msg0, g_msg0);
    cudaGetSymbolAddress((void**)&deg0, g_deg0);
    cudaGetSymbolAddress((void**)&h1,   g_h1);
    cudaGetSymbolAddress((void**)&msg1, g_msg1);
    cudaGetSymbolAddress((void**)&deg1, g_deg1);
    cudaGetSymbolAddress((void**)&h2,   g_h2);
    cudaGetSymbolAddress((void**)&msg2, g_msg2);
    cudaGetSymbolAddress((void**)&deg2, g_deg2);

    const int TPB = 256;

    // ======================= Layer 0 =======================
    {
        int n4 = N_DST0 * IN_FEATS / 4;
        zero_kernel<<<cdiv(n4, TPB), TPB>>>(msg0, n4);
        zero_kernel_s<<<cdiv(N_DST0, TPB), TPB>>>(deg0, N_DST0);

        long long threads = (long long)N_EDGE0 * (IN_FEATS / 4);
        aggregate_kernel<IN_FEATS><<<(int)((threads + TPB - 1) / TPB), TPB>>>(
            x, src0, dst0, msg0, deg0, N_EDGE0);

        inv_kernel<<<cdiv(N_DST0, TPB), TPB>>>(deg0, N_DST0);

        dim3 grid(N_HIDDEN / 128, N_DST0 / 128);
        gemm2_tc_kernel<true><<<grid, 256>>>(x, msg0, deg0, Ws0, Wn0, b0, h1,
                                             N_DST0, N_HIDDEN, IN_FEATS);
    }

    // ======================= Layer 1 =======================
    {
        int n4 = N_DST1 * N_HIDDEN / 4;
        zero_kernel<<<cdiv(n4, TPB), TPB>>>(msg1, n4);
        zero_kernel_s<<<cdiv(N_DST1, TPB), TPB>>>(deg1, N_DST1);

        long long threads = (long long)N_EDGE1 * (N_HIDDEN / 4);
        aggregate_kernel<N_HIDDEN><<<(int)((threads + TPB - 1) / TPB), TPB>>>(
            h1, src1, dst1, msg1, deg1, N_EDGE1);

        inv_kernel<<<cdiv(N_DST1, TPB), TPB>>>(deg1, N_DST1);

        dim3 grid(N_HIDDEN / 128, N_DST1 / 128);
        gemm2_tc_kernel<true><<<grid, 256>>>(h1, msg1, deg1, Ws1, Wn1, b1, h2,
                                             N_DST1, N_HIDDEN, N_HIDDEN);
    }

    // ======================= Layer 2 =======================
    {
        int n4 = N_DST2 * N_HIDDEN / 4;
        zero_kernel<<<cdiv(n4, TPB), TPB>>>(msg2, n4);
        zero_kernel_s<<<cdiv(N_DST2, TPB), TPB>>>(deg2, N_DST2);

        long long threads = (long long)N_EDGE2 * (N_HIDDEN / 4);
        aggregate_kernel<N_HIDDEN><<<(int)((threads + TPB - 1) / TPB), TPB>>>(
            h2, src2, dst2, msg2, deg2, N_EDGE2);

        inv_kernel<<<cdiv(N_DST2, TPB), TPB>>>(deg2, N_DST2);

        dim3 grid(cdiv(N_CLASSES, 64), N_DST2 / 128);
        gemm2_kernel<false><<<grid, 256>>>(h2, msg2, deg2, Ws2, Wn2, b2, out,
                                           N_DST2, N_CLASSES, N_HIDDEN);
    }

    (void)in_sizes; (void)n_in; (void)out_size;
}

// round 4
// speedup vs baseline: 1.5476x; 1.0414x over previous
#include <cuda_runtime.h>
#include <cuda_bf16.h>
#include <cstdint>

// ---------------------------------------------------------------------------
// Problem constants
// ---------------------------------------------------------------------------
#define N_SRC0 700000
#define N_DST0 51200
#define N_DST1 5120
#define N_DST2 1024
#define N_EDGE0 768000
#define N_EDGE1 51200
#define N_EDGE2 5120
#define IN_FEATS 128
#define N_HIDDEN 256
#define N_CLASSES 47

// ---------------------------------------------------------------------------
// Scratch (__device__ globals; 16B aligned for float4 / red.v4)
// ---------------------------------------------------------------------------
__device__ __align__(16) float g_msg0[(size_t)N_DST0 * IN_FEATS];
__device__ __align__(16) float g_deg0[N_DST0];
__device__ __align__(16) float g_h1[(size_t)N_DST0 * N_HIDDEN];
__device__ __align__(16) float g_msg1[(size_t)N_DST1 * N_HIDDEN];
__device__ __align__(16) float g_deg1[N_DST1];
__device__ __align__(16) float g_h2[(size_t)N_DST1 * N_HIDDEN];
__device__ __align__(16) float g_msg2[(size_t)N_DST2 * N_HIDDEN];
__device__ __align__(16) float g_deg2[N_DST2];

// ---------------------------------------------------------------------------
// Helpers
// ---------------------------------------------------------------------------
__device__ __forceinline__ void red_add_v4(float* addr, float4 v) {
    asm volatile("red.global.add.v4.f32 [%0], {%1, %2, %3, %4};"
                 :: "l"(addr), "f"(v.x), "f"(v.y), "f"(v.z), "f"(v.w)
                 : "memory");
}

__device__ __forceinline__ uint32_t f2tf32(float f) {
    uint32_t u;
    asm("cvt.rna.tf32.f32 %0, %1;" : "=r"(u) : "f"(f));
    return u;
}

__device__ __forceinline__ void mma_tf32(float& c0, float& c1, float& c2, float& c3,
                                         uint32_t a0, uint32_t a1, uint32_t a2, uint32_t a3,
                                         uint32_t b0, uint32_t b1) {
    asm volatile("mma.sync.aligned.m16n8k8.row.col.f32.tf32.tf32.f32 "
                 "{%0,%1,%2,%3}, {%4,%5,%6,%7}, {%8,%9}, {%0,%1,%2,%3};"
                 : "+f"(c0), "+f"(c1), "+f"(c2), "+f"(c3)
                 : "r"(a0), "r"(a1), "r"(a2), "r"(a3), "r"(b0), "r"(b1));
}

// inverse degree, computed inline where needed
__device__ __forceinline__ float inv_deg(float d) {
    return __fdividef(1.0f, fmaxf(d, 1.0f));
}

// ---------------------------------------------------------------------------
// Fused zero: msg (na4 float4) + deg (nb4 float4) in one launch
// ---------------------------------------------------------------------------
__global__ void zero2_kernel(float4* __restrict__ a, int na4,
                             float4* __restrict__ b, int nb4) {
    int i = blockIdx.x * blockDim.x + threadIdx.x;
    float4 z = make_float4(0.f, 0.f, 0.f, 0.f);
    if (i < na4) {
        a[i] = z;
    } else {
        int j = i - na4;
        if (j < nb4) b[j] = z;
    }
}

// ---------------------------------------------------------------------------
// Edge aggregation: msg[dst] += h[src], deg[dst] += 1
// Gather uses __ldcs (evict-first) so the streaming source rows do not
// evict the L2-resident msg accumulator that the REDs target.
// ---------------------------------------------------------------------------
template <int F>
__global__ __launch_bounds__(256)
void aggregate_kernel(const float* __restrict__ h,
                      const int* __restrict__ src,
                      const int* __restrict__ dst,
                      float* __restrict__ msg,
                      float* __restrict__ deg,
                      int n_edge) {
    constexpr int LPE = F / 4;
    int gtid = blockIdx.x * blockDim.x + threadIdx.x;
    int e    = gtid / LPE;
    int lane = gtid % LPE;
    if (e >= n_edge) return;

    int s = src[e];
    int d = dst[e];

    float4 v = __ldcs(reinterpret_cast<const float4*>(h + (size_t)s * F) + lane);
    red_add_v4(msg + (size_t)d * F + (size_t)lane * 4, v);

    if (lane == 0) atomicAdd(&deg[d], 1.0f);
}

// ---------------------------------------------------------------------------
// tf32 tensor-core dual GEMM:
//   C = A1 @ B1 + diag(1/max(deg,1)) * A2 @ B2 + bias   (+ optional ReLU)
// Requires: M % 128 == 0, N % 128 == 0, K % 32 == 0, 16B-aligned pointers.
// ---------------------------------------------------------------------------
template <bool RELU>
__global__ __launch_bounds__(256)
void gemm2_tc_kernel(const float* __restrict__ A1, const float* __restrict__ A2,
                     const float* __restrict__ deg,
                     const float* __restrict__ B1, const float* __restrict__ B2,
                     const float* __restrict__ bias, float* __restrict__ C,
                     int M, int N, int K) {
    constexpr int BM = 128, BN = 128, BK = 32;

    __shared__ uint32_t As[BM][BK + 4];
    __shared__ uint32_t Bs[BK][BN + 8];

    const int tid   = threadIdx.x;
    const int warp  = tid >> 5;
    const int lane  = tid & 31;
    const int g     = lane >> 2;
    const int t     = lane & 3;
    const int warpM = (warp & 1) * 64;
    const int warpN = (warp >> 1) * 32;
    const int rowBase = blockIdx.y * BM;
    const int colBase = blockIdx.x * BN;

    float acc[4][4][4];
#pragma unroll
    for (int i = 0; i < 4; ++i)
#pragma unroll
        for (int j = 0; j < 4; ++j)
#pragma unroll
            for (int r = 0; r < 4; ++r) acc[i][j][r] = 0.f;

#pragma unroll
    for (int phase = 0; phase < 2; ++phase) {
        const float* __restrict__ A = phase ? A2 : A1;
        const float* __restrict__ B = phase ? B2 : B1;

        for (int k0 = 0; k0 < K; k0 += BK) {
            // --- A tile: 128x32 floats = 1024 float4, 4 per thread ---
#pragma unroll
            for (int i = 0; i < 4; ++i) {
                int idx = i * 256 + tid;
                int row = idx >> 3;
                int c4  = idx & 7;
                float4 v = *reinterpret_cast<const float4*>(
                    A + (size_t)(rowBase + row) * K + k0 + c4 * 4);
                if (phase == 1) {
                    float s = inv_deg(deg[rowBase + row]);
                    v.x *= s; v.y *= s; v.z *= s; v.w *= s;
                }
                uint4 u = make_uint4(f2tf32(v.x), f2tf32(v.y), f2tf32(v.z), f2tf32(v.w));
                *reinterpret_cast<uint4*>(&As[row][c4 * 4]) = u;
            }
            // --- B tile: 32x128 floats = 1024 float4, 4 per thread ---
#pragma unroll
            for (int i = 0; i < 4; ++i) {
                int idx = i * 256 + tid;
                int row = idx >> 5;
                int c4  = idx & 31;
                float4 v = *reinterpret_cast<const float4*>(
                    B + (size_t)(k0 + row) * N + colBase + c4 * 4);
                uint4 u = make_uint4(f2tf32(v.x), f2tf32(v.y), f2tf32(v.z), f2tf32(v.w));
                *reinterpret_cast<uint4*>(&Bs[row][c4 * 4]) = u;
            }
            __syncthreads();

#pragma unroll
            for (int ks = 0; ks < BK / 8; ++ks) {
                const int kb = ks * 8;
                uint32_t af[4][4];
#pragma unroll
                for (int mt = 0; mt < 4; ++mt) {
                    int m = warpM + mt * 16;
                    af[mt][0] = As[m + g][kb + t];
                    af[mt][1] = As[m + 8 + g][kb + t];
                    af[mt][2] = As[m + g][kb + 4 + t];
                    af[mt][3] = As[m + 8 + g][kb + 4 + t];
                }
                uint32_t bf[4][2];
#pragma unroll
                for (int nt = 0; nt < 4; ++nt) {
                    int n = warpN + nt * 8;
                    bf[nt][0] = Bs[kb + t][n + g];
                    bf[nt][1] = Bs[kb + 4 + t][n + g];
                }
#pragma unroll
                for (int mt = 0; mt < 4; ++mt)
#pragma unroll
                    for (int nt = 0; nt < 4; ++nt)
                        mma_tf32(acc[mt][nt][0], acc[mt][nt][1],
                                 acc[mt][nt][2], acc[mt][nt][3],
                                 af[mt][0], af[mt][1], af[mt][2], af[mt][3],
                                 bf[nt][0], bf[nt][1]);
            }
            __syncthreads();
        }
    }

#pragma unroll
    for (int mt = 0; mt < 4; ++mt) {
#pragma unroll
        for (int nt = 0; nt < 4; ++nt) {
            int c  = colBase + warpN + nt * 8 + 2 * t;
            float bx = bias[c], by = bias[c + 1];
            int r0 = rowBase + warpM + mt * 16 + g;
            float v0 = acc[mt][nt][0] + bx;
            float v1 = acc[mt][nt][1] + by;
            float v2 = acc[mt][nt][2] + bx;
            float v3 = acc[mt][nt][3] + by;
            if (RELU) {
                v0 = fmaxf(v0, 0.f); v1 = fmaxf(v1, 0.f);
                v2 = fmaxf(v2, 0.f); v3 = fmaxf(v3, 0.f);
            }
            *reinterpret_cast<float2*>(C + (size_t)r0 * N + c)       = make_float2(v0, v1);
            *reinterpret_cast<float2*>(C + (size_t)(r0 + 8) * N + c) = make_float2(v2, v3);
        }
    }
}

// ---------------------------------------------------------------------------
// SIMT dual GEMM (layer 2: N=47). A2 rows scaled by 1/max(deg,1) at load.
// ---------------------------------------------------------------------------
template <bool RELU>
__global__ __launch_bounds__(256)
void gemm2_kernel(const float* __restrict__ A1, const float* __restrict__ A2,
                  const float* __restrict__ deg,
                  const float* __restrict__ B1, const float* __restrict__ B2,
                  const float* __restrict__ bias, float* __restrict__ C,
                  int M, int N, int K) {
    constexpr int BM = 128, BN = 64, BK = 16, TM = 8, TN = 4;

    __shared__ float As[BK][BM];
    __shared__ float Bs[BK][BN];

    const int tid = threadIdx.x;
    const int tx  = tid & 15;
    const int ty  = tid >> 4;
    const int rowBase = blockIdx.y * BM;
    const int colBase = blockIdx.x * BN;
    const bool nvec = (N & 3) == 0;

    float acc[TM][TN];
#pragma unroll
    for (int i = 0; i < TM; ++i)
#pragma unroll
        for (int j = 0; j < TN; ++j) acc[i][j] = 0.f;

#pragma unroll
    for (int phase = 0; phase < 2; ++phase) {
        const float* __restrict__ A = phase ? A2 : A1;
        const float* __restrict__ B = phase ? B2 : B1;

        for (int k0 = 0; k0 < K; k0 += BK) {
#pragma unroll
            for (int i = 0; i < 2; ++i) {
                int idx  = tid * 2 + i;
                int aRow = idx >> 2;
                int aC4  = idx & 3;
                float4 v = *reinterpret_cast<const float4*>(
                    A + (size_t)(rowBase + aRow) * K + k0 + aC4 * 4);
                if (phase == 1) {
                    float s = inv_deg(deg[rowBase + aRow]);
                    v.x *= s; v.y *= s; v.z *= s; v.w *= s;
                }
                As[aC4 * 4 + 0][aRow] = v.x;
                As[aC4 * 4 + 1][aRow] = v.y;
                As[aC4 * 4 + 2][aRow] = v.z;
                As[aC4 * 4 + 3][aRow] = v.w;
            }
            {
                int bRow = tid >> 4;
                int bC4  = tid & 15;
                int col  = colBase + bC4 * 4;
                const float* bp = B + (size_t)(k0 + bRow) * N;
                float4 v;
                if (nvec && col + 3 < N) {
                    v = *reinterpret_cast<const float4*>(bp + col);
                } else {
                    v.x = (col + 0 < N) ? bp[col + 0] : 0.f;
                    v.y = (col + 1 < N) ? bp[col + 1] : 0.f;
                    v.z = (col + 2 < N) ? bp[col + 2] : 0.f;
                    v.w = (col + 3 < N) ? bp[col + 3] : 0.f;
                }
                *reinterpret_cast<float4*>(&Bs[bRow][bC4 * 4]) = v;
            }
            __syncthreads();

#pragma unroll
            for (int kk = 0; kk < BK; ++kk) {
                float a[TM];
#pragma unroll
                for (int i = 0; i < TM; ++i) a[i] = As[kk][ty * TM + i];
                float4 bv = *reinterpret_cast<float4*>(&Bs[kk][tx * TN]);
                float b[TN] = {bv.x, bv.y, bv.z, bv.w};
#pragma unroll
                for (int i = 0; i < TM; ++i)
#pragma unroll
                    for (int j = 0; j < TN; ++j) acc[i][j] += a[i] * b[j];
            }
            __syncthreads();
        }
    }

#pragma unroll
    for (int i = 0; i < TM; ++i) {
        int r = rowBase + ty * TM + i;
#pragma unroll
        for (int j = 0; j < TN; ++j) {
            int c = colBase + tx * TN + j;
            if (c < N) {
                float v = acc[i][j] + bias[c];
                if (RELU) v = fmaxf(v, 0.f);
                C[(size_t)r * N + c] = v;
            }
        }
    }
}

// ---------------------------------------------------------------------------
// Launch
// ---------------------------------------------------------------------------
static inline int cdiv(int a, int b) { return (a + b - 1) / b; }

extern "C" void kernel_launch(void* const* d_in, const int* in_sizes, int n_in,
                              void* d_out, int out_size) {
    const float* x    = (const float*)d_in[0];
    const int*   src0 = (const int*)d_in[1];
    const int*   dst0 = (const int*)d_in[2];
    const int*   src1 = (const int*)d_in[3];
    const int*   dst1 = (const int*)d_in[4];
    const int*   src2 = (const int*)d_in[5];
    const int*   dst2 = (const int*)d_in[6];
    const float* Ws0  = (const float*)d_in[7];
    const float* Wn0  = (const float*)d_in[8];
    const float* b0   = (const float*)d_in[9];
    const float* Ws1  = (const float*)d_in[10];
    const float* Wn1  = (const float*)d_in[11];
    const float* b1   = (const float*)d_in[12];
    const float* Ws2  = (const float*)d_in[13];
    const float* Wn2  = (const float*)d_in[14];
    const float* b2   = (const float*)d_in[15];
    float* out = (float*)d_out;

    float *msg0, *deg0, *h1, *msg1, *deg1, *h2, *msg2, *deg2;
    cudaGetSymbolAddress((void**)&msg0, g_msg0);
    cudaGetSymbolAddress((void**)&deg0, g_deg0);
    cudaGetSymbolAddress((void**)&h1,   g_h1);
    cudaGetSymbolAddress((void**)&msg1, g_msg1);
    cudaGetSymbolAddress((void**)&deg1, g_deg1);
    cudaGetSymbolAddress((void**)&h2,   g_h2);
    cudaGetSymbolAddress((void**)&msg2, g_msg2);
    cudaGetSymbolAddress((void**)&deg2, g_deg2);

    const int TPB = 256;

    // ======================= Layer 0 =======================
    {
        int na4 = N_DST0 * IN_FEATS / 4, nb4 = N_DST0 / 4;
        zero2_kernel<<<cdiv(na4 + nb4, TPB), TPB>>>(
            (float4*)msg0, na4, (float4*)deg0, nb4);

        long long threads = (long long)N_EDGE0 * (IN_FEATS / 4);
        aggregate_kernel<IN_FEATS><<<(int)((threads + TPB - 1) / TPB), TPB>>>(
            x, src0, dst0, msg0, deg0, N_EDGE0);

        dim3 grid(N_HIDDEN / 128, N_DST0 / 128);
        gemm2_tc_kernel<true><<<grid, 256>>>(x, msg0, deg0, Ws0, Wn0, b0, h1,
                                             N_DST0, N_HIDDEN, IN_FEATS);
    }

    // ======================= Layer 1 =======================
    {
        int na4 = N_DST1 * N_HIDDEN / 4, nb4 = N_DST1 / 4;
        zero2_kernel<<<cdiv(na4 + nb4, TPB), TPB>>>(
            (float4*)msg1, na4, (float4*)deg1, nb4);

        long long threads = (long long)N_EDGE1 * (N_HIDDEN / 4);
        aggregate_kernel<N_HIDDEN><<<(int)((threads + TPB - 1) / TPB), TPB>>>(
            h1, src1, dst1, msg1, deg1, N_EDGE1);

        dim3 grid(N_HIDDEN / 128, N_DST1 / 128);
        gemm2_tc_kernel<true><<<grid, 256>>>(h1, msg1, deg1, Ws1, Wn1, b1, h2,
                                             N_DST1, N_HIDDEN, N_HIDDEN);
    }

    // ======================= Layer 2 =======================
    {
        int na4 = N_DST2 * N_HIDDEN / 4, nb4 = N_DST2 / 4;
        zero2_kernel<<<cdiv(na4 + nb4, TPB), TPB>>>(
            (float4*)msg2, na4, (float4*)deg2, nb4);

        long long threads = (long long)N_EDGE2 * (N_HIDDEN / 4);
        aggregate_kernel<N_HIDDEN><<<(int)((threads + TPB - 1) / TPB), TPB>>>(
            h2, src2, dst2, msg2, deg2, N_EDGE2);

        dim3 grid(cdiv(N_CLASSES, 64), N_DST2 / 128);
        gemm2_kernel<false><<<grid, 256>>>(h2, msg2, deg2, Ws2, Wn2, b2, out,
                                           N_DST2, N_CLASSES, N_HIDDEN);
    }

    (void)in_sizes; (void)n_in; (void)out_size;
}

// round 5
// speedup vs baseline: 1.8707x; 1.2088x over previous
#include <cuda_runtime.h>
#include <cuda_bf16.h>
#include <cstdint>

// ---------------------------------------------------------------------------
// Problem constants
// ---------------------------------------------------------------------------
#define N_SRC0 700000
#define N_DST0 51200
#define N_DST1 5120
#define N_DST2 1024
#define N_EDGE0 768000
#define N_EDGE1 51200
#define N_EDGE2 5120
#define IN_FEATS 128
#define N_HIDDEN 256
#define N_CLASSES 47

// ---------------------------------------------------------------------------
// Scratch (__device__ globals; 16B aligned for float4 / red.v4)
// ---------------------------------------------------------------------------
__device__ __align__(16) float g_msg0[(size_t)N_DST0 * IN_FEATS];
__device__ __align__(16) float g_deg0[N_DST0];
__device__ __align__(16) float g_h1[(size_t)N_DST0 * N_HIDDEN];
__device__ __align__(16) float g_msg1[(size_t)N_DST1 * N_HIDDEN];
__device__ __align__(16) float g_deg1[N_DST1];
__device__ __align__(16) float g_h2[(size_t)N_DST1 * N_HIDDEN];
__device__ __align__(16) float g_msg2[(size_t)N_DST2 * N_HIDDEN];
__device__ __align__(16) float g_deg2[N_DST2];

// ---------------------------------------------------------------------------
// Helpers
// ---------------------------------------------------------------------------
__device__ __forceinline__ void red_add_v4(float* addr, float4 v) {
    asm volatile("red.global.add.v4.f32 [%0], {%1, %2, %3, %4};"
                 :: "l"(addr), "f"(v.x), "f"(v.y), "f"(v.z), "f"(v.w)
                 : "memory");
}

__device__ __forceinline__ void red_add_f32(float* addr, float v) {
    asm volatile("red.global.add.f32 [%0], %1;" :: "l"(addr), "f"(v) : "memory");
}

__device__ __forceinline__ uint32_t f2tf32(float f) {
    uint32_t u;
    asm("cvt.rna.tf32.f32 %0, %1;" : "=r"(u) : "f"(f));
    return u;
}

__device__ __forceinline__ void mma_tf32(float& c0, float& c1, float& c2, float& c3,
                                         uint32_t a0, uint32_t a1, uint32_t a2, uint32_t a3,
                                         uint32_t b0, uint32_t b1) {
    asm volatile("mma.sync.aligned.m16n8k8.row.col.f32.tf32.tf32.f32 "
                 "{%0,%1,%2,%3}, {%4,%5,%6,%7}, {%8,%9}, {%0,%1,%2,%3};"
                 : "+f"(c0), "+f"(c1), "+f"(c2), "+f"(c3)
                 : "r"(a0), "r"(a1), "r"(a2), "r"(a3), "r"(b0), "r"(b1));
}

__device__ __forceinline__ float inv_deg(float d) {
    return __fdividef(1.0f, fmaxf(d, 1.0f));
}

// ---------------------------------------------------------------------------
// One fused init kernel: zero all msg/deg buffers; out = bias2 broadcast.
// ---------------------------------------------------------------------------
#define F4_MSG0 (N_DST0 * IN_FEATS / 4)
#define F4_DEG0 (N_DST0 / 4)
#define F4_MSG1 (N_DST1 * N_HIDDEN / 4)
#define F4_DEG1 (N_DST1 / 4)
#define F4_MSG2 (N_DST2 * N_HIDDEN / 4)
#define F4_DEG2 (N_DST2 / 4)
#define F4_TOTAL (F4_MSG0 + F4_DEG0 + F4_MSG1 + F4_DEG1 + F4_MSG2 + F4_DEG2)
#define OUT_ELEMS (N_DST2 * N_CLASSES)

__global__ void init_kernel(float4* __restrict__ msg0, float4* __restrict__ deg0,
                            float4* __restrict__ msg1, float4* __restrict__ deg1,
                            float4* __restrict__ msg2, float4* __restrict__ deg2,
                            float* __restrict__ out, const float* __restrict__ bias2) {
    int i = blockIdx.x * blockDim.x + threadIdx.x;
    float4 z = make_float4(0.f, 0.f, 0.f, 0.f);
    if (i < F4_TOTAL) {
        int j = i;
        if (j < F4_MSG0) { msg0[j] = z; return; }
        j -= F4_MSG0;
        if (j < F4_DEG0) { deg0[j] = z; return; }
        j -= F4_DEG0;
        if (j < F4_MSG1) { msg1[j] = z; return; }
        j -= F4_MSG1;
        if (j < F4_DEG1) { deg1[j] = z; return; }
        j -= F4_DEG1;
        if (j < F4_MSG2) { msg2[j] = z; return; }
        j -= F4_MSG2;
        deg2[j] = z;
        return;
    }
    int j = i - F4_TOTAL;
    if (j < OUT_ELEMS) out[j] = bias2[j % N_CLASSES];
}

// ---------------------------------------------------------------------------
// Edge aggregation: msg[dst] += h[src], deg[dst] += 1
// ---------------------------------------------------------------------------
template <int F>
__global__ __launch_bounds__(256)
void aggregate_kernel(const float* __restrict__ h,
                      const int* __restrict__ src,
                      const int* __restrict__ dst,
                      float* __restrict__ msg,
                      float* __restrict__ deg,
                      int n_edge) {
    constexpr int LPE = F / 4;
    int gtid = blockIdx.x * blockDim.x + threadIdx.x;
    int e    = gtid / LPE;
    int lane = gtid % LPE;
    if (e >= n_edge) return;

    int s = src[e];
    int d = dst[e];

    float4 v = __ldcs(reinterpret_cast<const float4*>(h + (size_t)s * F) + lane);
    red_add_v4(msg + (size_t)d * F + (size_t)lane * 4, v);

    if (lane == 0) red_add_f32(&deg[d], 1.0f);
}

// ---------------------------------------------------------------------------
// tf32 tensor-core dual GEMM (layers 0 and 1):
//   C = A1 @ B1 + diag(1/max(deg,1)) * A2 @ B2 + bias   (+ optional ReLU)
// Requires: M % 128 == 0, N % 128 == 0, K % 32 == 0.
// ---------------------------------------------------------------------------
template <bool RELU>
__global__ __launch_bounds__(256)
void gemm2_tc_kernel(const float* __restrict__ A1, const float* __restrict__ A2,
                     const float* __restrict__ deg,
                     const float* __restrict__ B1, const float* __restrict__ B2,
                     const float* __restrict__ bias, float* __restrict__ C,
                     int M, int N, int K) {
    constexpr int BM = 128, BN = 128, BK = 32;

    __shared__ uint32_t As[BM][BK + 4];
    __shared__ uint32_t Bs[BK][BN + 8];

    const int tid   = threadIdx.x;
    const int warp  = tid >> 5;
    const int lane  = tid & 31;
    const int g     = lane >> 2;
    const int t     = lane & 3;
    const int warpM = (warp & 1) * 64;
    const int warpN = (warp >> 1) * 32;
    const int rowBase = blockIdx.y * BM;
    const int colBase = blockIdx.x * BN;

    float acc[4][4][4];
#pragma unroll
    for (int i = 0; i < 4; ++i)
#pragma unroll
        for (int j = 0; j < 4; ++j)
#pragma unroll
            for (int r = 0; r < 4; ++r) acc[i][j][r] = 0.f;

#pragma unroll
    for (int phase = 0; phase < 2; ++phase) {
        const float* __restrict__ A = phase ? A2 : A1;
        const float* __restrict__ B = phase ? B2 : B1;

        for (int k0 = 0; k0 < K; k0 += BK) {
#pragma unroll
            for (int i = 0; i < 4; ++i) {
                int idx = i * 256 + tid;
                int row = idx >> 3;
                int c4  = idx & 7;
                float4 v = *reinterpret_cast<const float4*>(
                    A + (size_t)(rowBase + row) * K + k0 + c4 * 4);
                if (phase == 1) {
                    float s = inv_deg(deg[rowBase + row]);
                    v.x *= s; v.y *= s; v.z *= s; v.w *= s;
                }
                uint4 u = make_uint4(f2tf32(v.x), f2tf32(v.y), f2tf32(v.z), f2tf32(v.w));
                *reinterpret_cast<uint4*>(&As[row][c4 * 4]) = u;
            }
#pragma unroll
            for (int i = 0; i < 4; ++i) {
                int idx = i * 256 + tid;
                int row = idx >> 5;
                int c4  = idx & 31;
                float4 v = *reinterpret_cast<const float4*>(
                    B + (size_t)(k0 + row) * N + colBase + c4 * 4);
                uint4 u = make_uint4(f2tf32(v.x), f2tf32(v.y), f2tf32(v.z), f2tf32(v.w));
                *reinterpret_cast<uint4*>(&Bs[row][c4 * 4]) = u;
            }
            __syncthreads();

#pragma unroll
            for (int ks = 0; ks < BK / 8; ++ks) {
                const int kb = ks * 8;
                uint32_t af[4][4];
#pragma unroll
                for (int mt = 0; mt < 4; ++mt) {
                    int m = warpM + mt * 16;
                    af[mt][0] = As[m + g][kb + t];
                    af[mt][1] = As[m + 8 + g][kb + t];
                    af[mt][2] = As[m + g][kb + 4 + t];
                    af[mt][3] = As[m + 8 + g][kb + 4 + t];
                }
                uint32_t bf[4][2];
#pragma unroll
                for (int nt = 0; nt < 4; ++nt) {
                    int n = warpN + nt * 8;
                    bf[nt][0] = Bs[kb + t][n + g];
                    bf[nt][1] = Bs[kb + 4 + t][n + g];
                }
#pragma unroll
                for (int mt = 0; mt < 4; ++mt)
#pragma unroll
                    for (int nt = 0; nt < 4; ++nt)
                        mma_tf32(acc[mt][nt][0], acc[mt][nt][1],
                                 acc[mt][nt][2], acc[mt][nt][3],
                                 af[mt][0], af[mt][1], af[mt][2], af[mt][3],
                                 bf[nt][0], bf[nt][1]);
            }
            __syncthreads();
        }
    }

#pragma unroll
    for (int mt = 0; mt < 4; ++mt) {
#pragma unroll
        for (int nt = 0; nt < 4; ++nt) {
            int c  = colBase + warpN + nt * 8 + 2 * t;
            float bx = bias[c], by = bias[c + 1];
            int r0 = rowBase + warpM + mt * 16 + g;
            float v0 = acc[mt][nt][0] + bx;
            float v1 = acc[mt][nt][1] + by;
            float v2 = acc[mt][nt][2] + bx;
            float v3 = acc[mt][nt][3] + by;
            if (RELU) {
                v0 = fmaxf(v0, 0.f); v1 = fmaxf(v1, 0.f);
                v2 = fmaxf(v2, 0.f); v3 = fmaxf(v3, 0.f);
            }
            *reinterpret_cast<float2*>(C + (size_t)r0 * N + c)       = make_float2(v0, v1);
            *reinterpret_cast<float2*>(C + (size_t)(r0 + 8) * N + c) = make_float2(v2, v3);
        }
    }
}

// ---------------------------------------------------------------------------
// Layer-2 split-K tf32 GEMM:
//   C += A1 @ B1 + diag(1/max(deg,1)) * A2 @ B2
// C is pre-initialized with bias. N = 47 (padded to 64 in smem).
// grid.x = M/64, grid.y = 4 (bit1: phase, bit0: K-chunk of K/2).
// 128 threads: 4 warps, each owns 16 rows x 64 cols.
// ---------------------------------------------------------------------------
__global__ __launch_bounds__(128)
void gemm2_tc_splitk(const float* __restrict__ A1, const float* __restrict__ A2,
                     const float* __restrict__ deg,
                     const float* __restrict__ B1, const float* __restrict__ B2,
                     float* __restrict__ C, int M, int N, int K) {
    constexpr int BM = 64, BN = 64, BK = 32;

    __shared__ uint32_t As[BM][BK + 4];
    __shared__ uint32_t Bs[BK][BN + 8];

    const int tid   = threadIdx.x;
    const int warp  = tid >> 5;
    const int lane  = tid & 31;
    const int g     = lane >> 2;
    const int t     = lane & 3;
    const int warpM = warp * 16;
    const int rowBase = blockIdx.x * BM;

    const int phase  = blockIdx.y >> 1;
    const int kBegin = (blockIdx.y & 1) * (K / 2);
    const float* __restrict__ A = phase ? A2 : A1;
    const float* __restrict__ B = phase ? B2 : B1;

    float acc[8][4];
#pragma unroll
    for (int i = 0; i < 8; ++i)
#pragma unroll
        for (int r = 0; r < 4; ++r) acc[i][r] = 0.f;

    for (int k0 = kBegin; k0 < kBegin + K / 2; k0 += BK) {
        // A tile: 64x32 floats = 512 float4, 4 per thread
#pragma unroll
        for (int i = 0; i < 4; ++i) {
            int idx = i * 128 + tid;
            int row = idx >> 3;
            int c4  = idx & 7;
            float4 v = *reinterpret_cast<const float4*>(
                A + (size_t)(rowBase + row) * K + k0 + c4 * 4);
            if (phase == 1) {
                float s = inv_deg(deg[rowBase + row]);
                v.x *= s; v.y *= s; v.z *= s; v.w *= s;
            }
            uint4 u = make_uint4(f2tf32(v.x), f2tf32(v.y), f2tf32(v.z), f2tf32(v.w));
            *reinterpret_cast<uint4*>(&As[row][c4 * 4]) = u;
        }
        // B tile: 32 x 47 -> padded 64, scalar guarded loads (rows unaligned)
#pragma unroll
        for (int i = 0; i < 16; ++i) {
            int idx = i * 128 + tid;       // 0..2047
            int row = idx >> 6;            // 0..31
            int col = idx & 63;            // 0..63
            float v = (col < N) ? B[(size_t)(k0 + row) * N + col] : 0.f;
            Bs[row][col] = f2tf32(v);
        }
        __syncthreads();

#pragma unroll
        for (int ks = 0; ks < BK / 8; ++ks) {
            const int kb = ks * 8;
            uint32_t a0 = As[warpM + g][kb + t];
            uint32_t a1 = As[warpM + 8 + g][kb + t];
            uint32_t a2 = As[warpM + g][kb + 4 + t];
            uint32_t a3 = As[warpM + 8 + g][kb + 4 + t];
#pragma unroll
            for (int nt = 0; nt < 8; ++nt) {
                uint32_t b0 = Bs[kb + t][nt * 8 + g];
                uint32_t b1 = Bs[kb + 4 + t][nt * 8 + g];
                mma_tf32(acc[nt][0], acc[nt][1], acc[nt][2], acc[nt][3],
                         a0, a1, a2, a3, b0, b1);
            }
        }
        __syncthreads();
    }

    // epilogue: atomic accumulate into C (pre-initialized with bias)
    int r0 = rowBase + warpM + g;
#pragma unroll
    for (int nt = 0; nt < 8; ++nt) {
        int c = nt * 8 + 2 * t;
        if (c < N) {
            red_add_f32(C + (size_t)r0 * N + c, acc[nt][0]);
            red_add_f32(C + (size_t)(r0 + 8) * N + c, acc[nt][2]);
        }
        if (c + 1 < N) {
            red_add_f32(C + (size_t)r0 * N + c + 1, acc[nt][1]);
            red_add_f32(C + (size_t)(r0 + 8) * N + c + 1, acc[nt][3]);
        }
    }
}

// ---------------------------------------------------------------------------
// Launch
// ---------------------------------------------------------------------------
static inline int cdiv(int a, int b) { return (a + b - 1) / b; }

extern "C" void kernel_launch(void* const* d_in, const int* in_sizes, int n_in,
                              void* d_out, int out_size) {
    const float* x    = (const float*)d_in[0];
    const int*   src0 = (const int*)d_in[1];
    const int*   dst0 = (const int*)d_in[2];
    const int*   src1 = (const int*)d_in[3];
    const int*   dst1 = (const int*)d_in[4];
    const int*   src2 = (const int*)d_in[5];
    const int*   dst2 = (const int*)d_in[6];
    const float* Ws0  = (const float*)d_in[7];
    const float* Wn0  = (const float*)d_in[8];
    const float* b0   = (const float*)d_in[9];
    const float* Ws1  = (const float*)d_in[10];
    const float* Wn1  = (const float*)d_in[11];
    const float* b1   = (const float*)d_in[12];
    const float* Ws2  = (const float*)d_in[13];
    const float* Wn2  = (const float*)d_in[14];
    const float* b2   = (const float*)d_in[15];
    float* out = (float*)d_out;

    float *msg0, *deg0, *h1, *msg1, *deg1, *h2, *msg2, *deg2;
    cudaGetSymbolAddress((void**)&msg0, g_msg0);
    cudaGetSymbolAddress((void**)&deg0, g_deg0);
    cudaGetSymbolAddress((void**)&h1,   g_h1);
    cudaGetSymbolAddress((void**)&msg1, g_msg1);
    cudaGetSymbolAddress((void**)&deg1, g_deg1);
    cudaGetSymbolAddress((void**)&h2,   g_h2);
    cudaGetSymbolAddress((void**)&msg2, g_msg2);
    cudaGetSymbolAddress((void**)&deg2, g_deg2);

    const int TPB = 256;

    // ---- one fused init: zero all msg/deg, out = bias2 ----
    init_kernel<<<cdiv(F4_TOTAL + OUT_ELEMS, TPB), TPB>>>(
        (float4*)msg0, (float4*)deg0, (float4*)msg1, (float4*)deg1,
        (float4*)msg2, (float4*)deg2, out, b2);

    // ======================= Layer 0 =======================
    {
        long long threads = (long long)N_EDGE0 * (IN_FEATS / 4);
        aggregate_kernel<IN_FEATS><<<(int)((threads + TPB - 1) / TPB), TPB>>>(
            x, src0, dst0, msg0, deg0, N_EDGE0);

        dim3 grid(N_HIDDEN / 128, N_DST0 / 128);
        gemm2_tc_kernel<true><<<grid, 256>>>(x, msg0, deg0, Ws0, Wn0, b0, h1,
                                             N_DST0, N_HIDDEN, IN_FEATS);
    }

    // ======================= Layer 1 =======================
    {
        long long threads = (long long)N_EDGE1 * (N_HIDDEN / 4);
        aggregate_kernel<N_HIDDEN><<<(int)((threads + TPB - 1) / TPB), TPB>>>(
            h1, src1, dst1, msg1, deg1, N_EDGE1);

        dim3 grid(N_HIDDEN / 128, N_DST1 / 128);
        gemm2_tc_kernel<true><<<grid, 256>>>(h1, msg1, deg1, Ws1, Wn1, b1, h2,
                                             N_DST1, N_HIDDEN, N_HIDDEN);
    }

    // ======================= Layer 2 =======================
    {
        long long threads = (long long)N_EDGE2 * (N_HIDDEN / 4);
        aggregate_kernel<N_HIDDEN><<<(int)((threads + TPB - 1) / TPB), TPB>>>(
            h2, src2, dst2, msg2, deg2, N_EDGE2);

        dim3 grid(N_DST2 / 64, 4);
        gemm2_tc_splitk<<<grid, 128>>>(h2, msg2, deg2, Ws2, Wn2, out,
                                       N_DST2, N_CLASSES, N_HIDDEN);
    }

    (void)in_sizes; (void)n_in; (void)out_size;
}

// round 6
// speedup vs baseline: 2.0429x; 1.0921x over previous
#include <cuda_runtime.h>
#include <cuda_bf16.h>
#include <cstdint>

// ---------------------------------------------------------------------------
// Problem constants
// ---------------------------------------------------------------------------
#define N_SRC0 700000
#define N_DST0 51200
#define N_DST1 5120
#define N_DST2 1024
#define N_EDGE0 768000
#define N_EDGE1 51200
#define N_EDGE2 5120
#define IN_FEATS 128
#define N_HIDDEN 256
#define N_CLASSES 47

// ---------------------------------------------------------------------------
// Scratch (__device__ globals; 16B aligned for float4 / red.v4)
// ---------------------------------------------------------------------------
__device__ __align__(16) float g_msg0[(size_t)N_DST0 * IN_FEATS];
__device__ __align__(16) float g_deg0[N_DST0];
__device__ __align__(16) float g_h1[(size_t)N_DST0 * N_HIDDEN];
__device__ __align__(16) float g_msg1[(size_t)N_DST1 * N_HIDDEN];
__device__ __align__(16) float g_deg1[N_DST1];
__device__ __align__(16) float g_h2[(size_t)N_DST1 * N_HIDDEN];
__device__ __align__(16) float g_msg2[(size_t)N_DST2 * N_HIDDEN];
__device__ __align__(16) float g_deg2[N_DST2];

// ---------------------------------------------------------------------------
// Helpers
// ---------------------------------------------------------------------------
__device__ __forceinline__ void red_add_v4(float* addr, float4 v) {
    asm volatile("red.global.add.v4.f32 [%0], {%1, %2, %3, %4};"
                 :: "l"(addr), "f"(v.x), "f"(v.y), "f"(v.z), "f"(v.w)
                 : "memory");
}

__device__ __forceinline__ void red_add_f32(float* addr, float v) {
    asm volatile("red.global.add.f32 [%0], %1;" :: "l"(addr), "f"(v) : "memory");
}

__device__ __forceinline__ uint32_t f2tf32(float f) {
    uint32_t u;
    asm("cvt.rna.tf32.f32 %0, %1;" : "=r"(u) : "f"(f));
    return u;
}

__device__ __forceinline__ void mma_tf32(float& c0, float& c1, float& c2, float& c3,
                                         uint32_t a0, uint32_t a1, uint32_t a2, uint32_t a3,
                                         uint32_t b0, uint32_t b1) {
    asm volatile("mma.sync.aligned.m16n8k8.row.col.f32.tf32.tf32.f32 "
                 "{%0,%1,%2,%3}, {%4,%5,%6,%7}, {%8,%9}, {%0,%1,%2,%3};"
                 : "+f"(c0), "+f"(c1), "+f"(c2), "+f"(c3)
                 : "r"(a0), "r"(a1), "r"(a2), "r"(a3), "r"(b0), "r"(b1));
}

__device__ __forceinline__ float inv_deg(float d) {
    return __fdividef(1.0f, fmaxf(d, 1.0f));
}

// ---------------------------------------------------------------------------
// One fused init kernel: zero all msg/deg buffers; out = bias2 broadcast.
// ---------------------------------------------------------------------------
#define F4_MSG0 (N_DST0 * IN_FEATS / 4)
#define F4_DEG0 (N_DST0 / 4)
#define F4_MSG1 (N_DST1 * N_HIDDEN / 4)
#define F4_DEG1 (N_DST1 / 4)
#define F4_MSG2 (N_DST2 * N_HIDDEN / 4)
#define F4_DEG2 (N_DST2 / 4)
#define F4_TOTAL (F4_MSG0 + F4_DEG0 + F4_MSG1 + F4_DEG1 + F4_MSG2 + F4_DEG2)
#define OUT_ELEMS (N_DST2 * N_CLASSES)

__global__ void init_kernel(float4* __restrict__ msg0, float4* __restrict__ deg0,
                            float4* __restrict__ msg1, float4* __restrict__ deg1,
                            float4* __restrict__ msg2, float4* __restrict__ deg2,
                            float* __restrict__ out, const float* __restrict__ bias2) {
    int i = blockIdx.x * blockDim.x + threadIdx.x;
    float4 z = make_float4(0.f, 0.f, 0.f, 0.f);
    if (i < F4_TOTAL) {
        int j = i;
        if (j < F4_MSG0) { msg0[j] = z; return; }
        j -= F4_MSG0;
        if (j < F4_DEG0) { deg0[j] = z; return; }
        j -= F4_DEG0;
        if (j < F4_MSG1) { msg1[j] = z; return; }
        j -= F4_MSG1;
        if (j < F4_DEG1) { deg1[j] = z; return; }
        j -= F4_DEG1;
        if (j < F4_MSG2) { msg2[j] = z; return; }
        j -= F4_MSG2;
        deg2[j] = z;
        return;
    }
    int j = i - F4_TOTAL;
    if (j < OUT_ELEMS) out[j] = bias2[j % N_CLASSES];
}

// ---------------------------------------------------------------------------
// Edge aggregation, ILP=2: each thread handles TWO float4 chunks of one
// edge's feature row (two independent gathers + two REDs) -> MLP 2.
// LPE = F/8 lanes per edge; lane handles f4 slots {lane, lane+LPE}.
// ---------------------------------------------------------------------------
template <int F>
__global__ __launch_bounds__(256)
void aggregate_kernel(const float* __restrict__ h,
                      const int* __restrict__ src,
                      const int* __restrict__ dst,
                      float* __restrict__ msg,
                      float* __restrict__ deg,
                      int n_edge) {
    constexpr int LPE = F / 8;                  // lanes per edge
    int gtid = blockIdx.x * blockDim.x + threadIdx.x;
    int e    = gtid / LPE;
    int lane = gtid % LPE;
    if (e >= n_edge) return;

    int s = src[e];
    int d = dst[e];

    const float4* row = reinterpret_cast<const float4*>(h + (size_t)s * F);
    float4 v0 = __ldcs(row + lane);
    float4 v1 = __ldcs(row + lane + LPE);

    float* mrow = msg + (size_t)d * F;
    red_add_v4(mrow + (size_t)lane * 4, v0);
    red_add_v4(mrow + (size_t)(lane + LPE) * 4, v1);

    if (lane == 0) red_add_f32(&deg[d], 1.0f);
}

// ---------------------------------------------------------------------------
// tf32 tensor-core dual GEMM (layers 0 and 1), full-width column tile:
//   C = A1 @ B1 + diag(1/max(deg,1)) * A2 @ B2 + bias   (+ optional ReLU)
// Requires: N == 256, M % 64 == 0, K % 32 == 0.
// BM=64, BN=256, BK=32; 256 threads = 8 warps (2 along M x 4 along N),
// warp tile 32x64 = 2 m-tiles x 8 n-tiles of m16n8k8.
// A (the big operand) is streamed from DRAM exactly once.
// ---------------------------------------------------------------------------
template <bool RELU>
__global__ __launch_bounds__(256, 2)
void gemm2_tc_kernel(const float* __restrict__ A1, const float* __restrict__ A2,
                     const float* __restrict__ deg,
                     const float* __restrict__ B1, const float* __restrict__ B2,
                     const float* __restrict__ bias, float* __restrict__ C,
                     int M, int N, int K) {
    constexpr int BM = 64, BN = 256, BK = 32;

    __shared__ uint32_t As[BM][BK + 4];   // 9.2 KB
    __shared__ uint32_t Bs[BK][BN + 8];   // 33.8 KB

    const int tid   = threadIdx.x;
    const int warp  = tid >> 5;
    const int lane  = tid & 31;
    const int g     = lane >> 2;
    const int t     = lane & 3;
    const int warpM = (warp & 1) * 32;
    const int warpN = (warp >> 1) * 64;
    const int rowBase = blockIdx.x * BM;

    float acc[2][8][4];
#pragma unroll
    for (int i = 0; i < 2; ++i)
#pragma unroll
        for (int j = 0; j < 8; ++j)
#pragma unroll
            for (int r = 0; r < 4; ++r) acc[i][j][r] = 0.f;

#pragma unroll
    for (int phase = 0; phase < 2; ++phase) {
        const float* __restrict__ A = phase ? A2 : A1;
        const float* __restrict__ B = phase ? B2 : B1;

        for (int k0 = 0; k0 < K; k0 += BK) {
            // --- A tile: 64x32 floats = 512 float4, 2 per thread ---
#pragma unroll
            for (int i = 0; i < 2; ++i) {
                int idx = i * 256 + tid;
                int row = idx >> 3;       // 0..63
                int c4  = idx & 7;        // 0..7
                float4 v = *reinterpret_cast<const float4*>(
                    A + (size_t)(rowBase + row) * K + k0 + c4 * 4);
                if (phase == 1) {
                    float s = inv_deg(deg[rowBase + row]);
                    v.x *= s; v.y *= s; v.z *= s; v.w *= s;
                }
                uint4 u = make_uint4(f2tf32(v.x), f2tf32(v.y), f2tf32(v.z), f2tf32(v.w));
                *reinterpret_cast<uint4*>(&As[row][c4 * 4]) = u;
            }
            // --- B tile: 32x256 floats = 2048 float4, 8 per thread ---
            // (weights: L2-resident after the first block)
#pragma unroll
            for (int i = 0; i < 8; ++i) {
                int idx = i * 256 + tid;
                int row = idx >> 6;       // 0..31
                int c4  = idx & 63;       // 0..63
                float4 v = *reinterpret_cast<const float4*>(
                    B + (size_t)(k0 + row) * N + c4 * 4);
                uint4 u = make_uint4(f2tf32(v.x), f2tf32(v.y), f2tf32(v.z), f2tf32(v.w));
                *reinterpret_cast<uint4*>(&Bs[row][c4 * 4]) = u;
            }
            __syncthreads();

#pragma unroll
            for (int ks = 0; ks < BK / 8; ++ks) {
                const int kb = ks * 8;
                uint32_t af[2][4];
#pragma unroll
                for (int mt = 0; mt < 2; ++mt) {
                    int m = warpM + mt * 16;
                    af[mt][0] = As[m + g][kb + t];
                    af[mt][1] = As[m + 8 + g][kb + t];
                    af[mt][2] = As[m + g][kb + 4 + t];
                    af[mt][3] = As[m + 8 + g][kb + 4 + t];
                }
                uint32_t bf[8][2];
#pragma unroll
                for (int nt = 0; nt < 8; ++nt) {
                    int n = warpN + nt * 8;
                    bf[nt][0] = Bs[kb + t][n + g];
                    bf[nt][1] = Bs[kb + 4 + t][n + g];
                }
#pragma unroll
                for (int mt = 0; mt < 2; ++mt)
#pragma unroll
                    for (int nt = 0; nt < 8; ++nt)
                        mma_tf32(acc[mt][nt][0], acc[mt][nt][1],
                                 acc[mt][nt][2], acc[mt][nt][3],
                                 af[mt][0], af[mt][1], af[mt][2], af[mt][3],
                                 bf[nt][0], bf[nt][1]);
            }
            __syncthreads();
        }
    }

    // --- epilogue: bias (+ReLU), float2 stores ---
#pragma unroll
    for (int mt = 0; mt < 2; ++mt) {
#pragma unroll
        for (int nt = 0; nt < 8; ++nt) {
            int c  = warpN + nt * 8 + 2 * t;
            float bx = bias[c], by = bias[c + 1];
            int r0 = rowBase + warpM + mt * 16 + g;
            float v0 = acc[mt][nt][0] + bx;
            float v1 = acc[mt][nt][1] + by;
            float v2 = acc[mt][nt][2] + bx;
            float v3 = acc[mt][nt][3] + by;
            if (RELU) {
                v0 = fmaxf(v0, 0.f); v1 = fmaxf(v1, 0.f);
                v2 = fmaxf(v2, 0.f); v3 = fmaxf(v3, 0.f);
            }
            *reinterpret_cast<float2*>(C + (size_t)r0 * N + c)       = make_float2(v0, v1);
            *reinterpret_cast<float2*>(C + (size_t)(r0 + 8) * N + c) = make_float2(v2, v3);
        }
    }
}

// ---------------------------------------------------------------------------
// Layer-2 split-K tf32 GEMM:
//   C += A1 @ B1 + diag(1/max(deg,1)) * A2 @ B2
// C is pre-initialized with bias. N = 47 (padded to 64 in smem).
// grid.x = M/64, grid.y = 4 (bit1: phase, bit0: K-chunk of K/2).
// ---------------------------------------------------------------------------
__global__ __launch_bounds__(128)
void gemm2_tc_splitk(const float* __restrict__ A1, const float* __restrict__ A2,
                     const float* __restrict__ deg,
                     const float* __restrict__ B1, const float* __restrict__ B2,
                     float* __restrict__ C, int M, int N, int K) {
    constexpr int BM = 64, BN = 64, BK = 32;

    __shared__ uint32_t As[BM][BK + 4];
    __shared__ uint32_t Bs[BK][BN + 8];

    const int tid   = threadIdx.x;
    const int warp  = tid >> 5;
    const int lane  = tid & 31;
    const int g     = lane >> 2;
    const int t     = lane & 3;
    const int warpM = warp * 16;
    const int rowBase = blockIdx.x * BM;

    const int phase  = blockIdx.y >> 1;
    const int kBegin = (blockIdx.y & 1) * (K / 2);
    const float* __restrict__ A = phase ? A2 : A1;
    const float* __restrict__ B = phase ? B2 : B1;

    float acc[8][4];
#pragma unroll
    for (int i = 0; i < 8; ++i)
#pragma unroll
        for (int r = 0; r < 4; ++r) acc[i][r] = 0.f;

    for (int k0 = kBegin; k0 < kBegin + K / 2; k0 += BK) {
#pragma unroll
        for (int i = 0; i < 4; ++i) {
            int idx = i * 128 + tid;
            int row = idx >> 3;
            int c4  = idx & 7;
            float4 v = *reinterpret_cast<const float4*>(
                A + (size_t)(rowBase + row) * K + k0 + c4 * 4);
            if (phase == 1) {
                float s = inv_deg(deg[rowBase + row]);
                v.x *= s; v.y *= s; v.z *= s; v.w *= s;
            }
            uint4 u = make_uint4(f2tf32(v.x), f2tf32(v.y), f2tf32(v.z), f2tf32(v.w));
            *reinterpret_cast<uint4*>(&As[row][c4 * 4]) = u;
        }
#pragma unroll
        for (int i = 0; i < 16; ++i) {
            int idx = i * 128 + tid;
            int row = idx >> 6;
            int col = idx & 63;
            float v = (col < N) ? B[(size_t)(k0 + row) * N + col] : 0.f;
            Bs[row][col] = f2tf32(v);
        }
        __syncthreads();

#pragma unroll
        for (int ks = 0; ks < BK / 8; ++ks) {
            const int kb = ks * 8;
            uint32_t a0 = As[warpM + g][kb + t];
            uint32_t a1 = As[warpM + 8 + g][kb + t];
            uint32_t a2 = As[warpM + g][kb + 4 + t];
            uint32_t a3 = As[warpM + 8 + g][kb + 4 + t];
#pragma unroll
            for (int nt = 0; nt < 8; ++nt) {
                uint32_t b0 = Bs[kb + t][nt * 8 + g];
                uint32_t b1 = Bs[kb + 4 + t][nt * 8 + g];
                mma_tf32(acc[nt][0], acc[nt][1], acc[nt][2], acc[nt][3],
                         a0, a1, a2, a3, b0, b1);
            }
        }
        __syncthreads();
    }

    int r0 = rowBase + warpM + g;
#pragma unroll
    for (int nt = 0; nt < 8; ++nt) {
        int c = nt * 8 + 2 * t;
        if (c < N) {
            red_add_f32(C + (size_t)r0 * N + c, acc[nt][0]);
            red_add_f32(C + (size_t)(r0 + 8) * N + c, acc[nt][2]);
        }
        if (c + 1 < N) {
            red_add_f32(C + (size_t)r0 * N + c + 1, acc[nt][1]);
            red_add_f32(C + (size_t)(r0 + 8) * N + c + 1, acc[nt][3]);
        }
    }
}

// ---------------------------------------------------------------------------
// Launch
// ---------------------------------------------------------------------------
static inline int cdiv(int a, int b) { return (a + b - 1) / b; }

extern "C" void kernel_launch(void* const* d_in, const int* in_sizes, int n_in,
                              void* d_out, int out_size) {
    const float* x    = (const float*)d_in[0];
    const int*   src0 = (const int*)d_in[1];
    const int*   dst0 = (const int*)d_in[2];
    const int*   src1 = (const int*)d_in[3];
    const int*   dst1 = (const int*)d_in[4];
    const int*   src2 = (const int*)d_in[5];
    const int*   dst2 = (const int*)d_in[6];
    const float* Ws0  = (const float*)d_in[7];
    const float* Wn0  = (const float*)d_in[8];
    const float* b0   = (const float*)d_in[9];
    const float* Ws1  = (const float*)d_in[10];
    const float* Wn1  = (const float*)d_in[11];
    const float* b1   = (const float*)d_in[12];
    const float* Ws2  = (const float*)d_in[13];
    const float* Wn2  = (const float*)d_in[14];
    const float* b2   = (const float*)d_in[15];
    float* out = (float*)d_out;

    float *msg0, *deg0, *h1, *msg1, *deg1, *h2, *msg2, *deg2;
    cudaGetSymbolAddress((void**)&msg0, g_msg0);
    cudaGetSymbolAddress((void**)&deg0, g_deg0);
    cudaGetSymbolAddress((void**)&h1,   g_h1);
    cudaGetSymbolAddress((void**)&msg1, g_msg1);
    cudaGetSymbolAddress((void**)&deg1, g_deg1);
    cudaGetSymbolAddress((void**)&h2,   g_h2);
    cudaGetSymbolAddress((void**)&msg2, g_msg2);
    cudaGetSymbolAddress((void**)&deg2, g_deg2);

    const int TPB = 256;

    // ---- one fused init: zero all msg/deg, out = bias2 ----
    init_kernel<<<cdiv(F4_TOTAL + OUT_ELEMS, TPB), TPB>>>(
        (float4*)msg0, (float4*)deg0, (float4*)msg1, (float4*)deg1,
        (float4*)msg2, (float4*)deg2, out, b2);

    // ======================= Layer 0 =======================
    {
        long long threads = (long long)N_EDGE0 * (IN_FEATS / 8);
        aggregate_kernel<IN_FEATS><<<(int)((threads + TPB - 1) / TPB), TPB>>>(
            x, src0, dst0, msg0, deg0, N_EDGE0);

        gemm2_tc_kernel<true><<<N_DST0 / 64, 256>>>(x, msg0, deg0, Ws0, Wn0, b0, h1,
                                                    N_DST0, N_HIDDEN, IN_FEATS);
    }

    // ======================= Layer 1 =======================
    {
        long long threads = (long long)N_EDGE1 * (N_HIDDEN / 8);
        aggregate_kernel<N_HIDDEN><<<(int)((threads + TPB - 1) / TPB), TPB>>>(
            h1, src1, dst1, msg1, deg1, N_EDGE1);

        gemm2_tc_kernel<true><<<N_DST1 / 64, 256>>>(h1, msg1, deg1, Ws1, Wn1, b1, h2,
                                                    N_DST1, N_HIDDEN, N_HIDDEN);
    }

    // ======================= Layer 2 =======================
    {
        long long threads = (long long)N_EDGE2 * (N_HIDDEN / 8);
        aggregate_kernel<N_HIDDEN><<<(int)((threads + TPB - 1) / TPB), TPB>>>(
            h2, src2, dst2, msg2, deg2, N_EDGE2);

        dim3 grid(N_DST2 / 64, 4);
        gemm2_tc_splitk<<<grid, 128>>>(h2, msg2, deg2, Ws2, Wn2, out,
                                       N_DST2, N_CLASSES, N_HIDDEN);
    }

    (void)in_sizes; (void)n_in; (void)out_size;
}